// round 4
// baseline (speedup 1.0000x reference)
#include <cuda_runtime.h>
#include <cuda_bf16.h>
#include <cstdint>

// Problem constants
#define E1C   600000
#define E2C   300000
#define N1C   100000
#define N2C   20000

// ---------------- scratch (device globals; no allocation allowed) ----------------
__device__ int   g_rowptr1[N1C + 1];
__device__ int   g_cursor1[N1C + 1];
__device__ int   g_perm1[E1C];
__device__ int   g_rowptr2[N2C + 1];
__device__ int   g_cursor2[N2C + 1];
__device__ int   g_perm2[E2C];
__device__ int   g_bs1[64];
__device__ int   g_bs2[64];
__device__ float g_z1[(size_t)N1C * 256];   // 102.4 MB
__device__ float g_h [(size_t)N1C * 64];    // 25.6 MB
__device__ float g_z2[(size_t)N2C * 256];   // 20.5 MB

// ---------------- packed f32x2 FMA (full-rate FFMA2 on sm_103a) ----------------
__device__ __forceinline__ float2 ffma2(float2 a, float2 b, float2 c) {
    float2 d;
    asm("fma.rn.f32x2 %0, %1, %2, %3;"
        : "=l"(reinterpret_cast<unsigned long long&>(d))
        : "l"(reinterpret_cast<unsigned long long&>(a)),
          "l"(reinterpret_cast<unsigned long long&>(b)),
          "l"(reinterpret_cast<unsigned long long&>(c)));
    return d;
}

// ---------------- counting-sort kernels ----------------
__global__ void k_zero(int* __restrict__ c1, int n1, int* __restrict__ c2, int n2) {
    int i = blockIdx.x * blockDim.x + threadIdx.x;
    if (i <= n1) c1[i] = 0;
    if (i <= n2) c2[i] = 0;
}

__global__ void k_hist(const int* __restrict__ dst1, const int* __restrict__ dst2,
                       int* __restrict__ c1, int* __restrict__ c2) {
    int i = blockIdx.x * blockDim.x + threadIdx.x;
    if (i < E1C) {
        atomicAdd(&c1[__ldg(dst1 + i)], 1);
    } else if (i < E1C + E2C) {
        atomicAdd(&c2[__ldg(dst2 + i - E1C)], 1);
    }
}

// per-block exclusive scan over 2048-element chunks
__global__ void k_scan_local(const int* __restrict__ cnt, int* __restrict__ excl,
                             int* __restrict__ bsums, int n) {
    const int t = threadIdx.x;
    const int base = blockIdx.x * 2048 + t * 8;
    int v[8], pre[8], s = 0;
#pragma unroll
    for (int j = 0; j < 8; j++) {
        int idx = base + j;
        v[j] = (idx < n) ? cnt[idx] : 0;
        pre[j] = s;
        s += v[j];
    }
    int lane = t & 31, wid = t >> 5;
    int inc = s;
#pragma unroll
    for (int off = 1; off < 32; off <<= 1) {
        int y = __shfl_up_sync(0xffffffffu, inc, off);
        if (lane >= off) inc += y;
    }
    __shared__ int wsum[8];
    __shared__ int wexcl[8];
    if (lane == 31) wsum[wid] = inc;
    __syncthreads();
    if (t == 0) {
        int run = 0;
        for (int w = 0; w < 8; w++) { wexcl[w] = run; run += wsum[w]; }
    }
    __syncthreads();
    int texcl = wexcl[wid] + inc - s;
#pragma unroll
    for (int j = 0; j < 8; j++) {
        int idx = base + j;
        if (idx < n) excl[idx] = texcl + pre[j];
    }
    if (t == 255) bsums[blockIdx.x] = wexcl[7] + wsum[7];
}

// one block scans both bsums arrays (<=64 entries each)
__global__ void k_scan_bsums2(int* __restrict__ bsA, int nA,
                              int* __restrict__ bsB, int nB) {
    __shared__ int sh[64];
    int t = threadIdx.x;
    int* bs = (blockIdx.x == 0) ? bsA : bsB;
    int nb  = (blockIdx.x == 0) ? nA : nB;
    int v = (t < nb) ? bs[t] : 0;
    int x = v;
    sh[t] = x;
    __syncthreads();
    for (int off = 1; off < 64; off <<= 1) {
        int y = (t >= off) ? sh[t - off] : 0;
        __syncthreads();
        x += y;
        sh[t] = x;
        __syncthreads();
    }
    if (t < nb) bs[t] = x - v;   // exclusive
}

__global__ void k_scan_add(int* __restrict__ rowptr, int* __restrict__ cursor,
                           const int* __restrict__ bsums, int n, int total) {
    int i = blockIdx.x * blockDim.x + threadIdx.x;
    if (i < n) {
        int f = rowptr[i] + bsums[i >> 11];
        rowptr[i] = f;
        cursor[i] = f;
    }
    if (i == 0) rowptr[n] = total;
}

__global__ void k_scatter(const int* __restrict__ dst1, const int* __restrict__ dst2,
                          int* __restrict__ cur1, int* __restrict__ cur2,
                          int* __restrict__ perm1, int* __restrict__ perm2) {
    int i = blockIdx.x * blockDim.x + threadIdx.x;
    if (i < E1C) {
        int p = atomicAdd(&cur1[__ldg(dst1 + i)], 1);
        perm1[p] = i;
    } else if (i < E1C + E2C) {
        int e = i - E1C;
        int p = atomicAdd(&cur2[__ldg(dst2 + e)], 1);
        perm2[p] = e;
    }
}

// ---------------- per-dst basis aggregation (one warp per dst) ----------------
// z[dst, b*64 + d] = sum_e comp[et_e,b]*norm_e*x[src_e, d]
// lane owns dims {2*lane, 2*lane+1} for all 4 bases -> no cross-lane traffic,
// no float atomics (edges are pre-sorted by dst).
__global__ void k_agg(const int* __restrict__ rowptr, const int* __restrict__ perm,
                      const int* __restrict__ src, const int* __restrict__ etype,
                      const float* __restrict__ norm, const int* __restrict__ inodes,
                      const float* __restrict__ x, const float* __restrict__ comp,
                      float* __restrict__ zout, int ndst) {
    int gw = (blockIdx.x * blockDim.x + threadIdx.x) >> 5;
    int lane = threadIdx.x & 31;
    if (gw >= ndst) return;

    float2 a0 = {0.f, 0.f}, a1 = {0.f, 0.f}, a2 = {0.f, 0.f}, a3 = {0.f, 0.f};
    int p = __ldg(rowptr + gw);
    const int pe = __ldg(rowptr + gw + 1);

    // 2-deep software pipeline for memory-level parallelism
    while (p + 2 <= pe) {
        int e0 = __ldg(perm + p), e1 = __ldg(perm + p + 1);
        int s0 = __ldg(src + e0), s1 = __ldg(src + e1);
        int t0 = __ldg(etype + e0), t1 = __ldg(etype + e1);
        float n0 = __ldg(norm + e0), n1 = __ldg(norm + e1);
        int nd0 = inodes ? __ldg(inodes + s0) : s0;
        int nd1 = inodes ? __ldg(inodes + s1) : s1;
        float2 x0 = __ldg((const float2*)(x + (size_t)nd0 * 64) + lane);
        float2 x1 = __ldg((const float2*)(x + (size_t)nd1 * 64) + lane);
        float4 c0 = __ldg((const float4*)(comp) + t0);
        float4 c1 = __ldg((const float4*)(comp) + t1);
        float w;
        w = c0.x * n0; a0.x = fmaf(w, x0.x, a0.x); a0.y = fmaf(w, x0.y, a0.y);
        w = c0.y * n0; a1.x = fmaf(w, x0.x, a1.x); a1.y = fmaf(w, x0.y, a1.y);
        w = c0.z * n0; a2.x = fmaf(w, x0.x, a2.x); a2.y = fmaf(w, x0.y, a2.y);
        w = c0.w * n0; a3.x = fmaf(w, x0.x, a3.x); a3.y = fmaf(w, x0.y, a3.y);
        w = c1.x * n1; a0.x = fmaf(w, x1.x, a0.x); a0.y = fmaf(w, x1.y, a0.y);
        w = c1.y * n1; a1.x = fmaf(w, x1.x, a1.x); a1.y = fmaf(w, x1.y, a1.y);
        w = c1.z * n1; a2.x = fmaf(w, x1.x, a2.x); a2.y = fmaf(w, x1.y, a2.y);
        w = c1.w * n1; a3.x = fmaf(w, x1.x, a3.x); a3.y = fmaf(w, x1.y, a3.y);
        p += 2;
    }
    if (p < pe) {
        int e0 = __ldg(perm + p);
        int s0 = __ldg(src + e0);
        int t0 = __ldg(etype + e0);
        float n0 = __ldg(norm + e0);
        int nd0 = inodes ? __ldg(inodes + s0) : s0;
        float2 x0 = __ldg((const float2*)(x + (size_t)nd0 * 64) + lane);
        float4 c0 = __ldg((const float4*)(comp) + t0);
        float w;
        w = c0.x * n0; a0.x = fmaf(w, x0.x, a0.x); a0.y = fmaf(w, x0.y, a0.y);
        w = c0.y * n0; a1.x = fmaf(w, x0.x, a1.x); a1.y = fmaf(w, x0.y, a1.y);
        w = c0.z * n0; a2.x = fmaf(w, x0.x, a2.x); a2.y = fmaf(w, x0.y, a2.y);
        w = c0.w * n0; a3.x = fmaf(w, x0.x, a3.x); a3.y = fmaf(w, x0.y, a3.y);
    }
    float2* zr = (float2*)(zout + (size_t)gw * 256);
    zr[lane]      = a0;   // basis 0: dims [0,64)
    zr[32 + lane] = a1;   // basis 1
    zr[64 + lane] = a2;   // basis 2
    zr[96 + lane] = a3;   // basis 3
}

// ---------------- dense projection GEMM: C[n,OUTD] = Z[n,256] @ W[256,OUTD] + bias ----------------
// FFMA2 inner kernel. z values duplicated {z,z} at smem-store time so W column
// pairs load as natural f32x2 operands; (BK+1) padding keeps LDS conflict-free.
template <int OUTD, bool RELU>
__global__ void k_gemm(const float* __restrict__ Z, const float* __restrict__ W,
                       const float* __restrict__ bias, float* __restrict__ C, int nrows) {
    constexpr int K = 256, BK = 32;
    constexpr int G = OUTD / 4;       // col groups of 4
    constexpr int TY = 256 / G;       // 16 (OUT=64) or 32 (OUT=32)
    constexpr int ROWS = 8 * TY;      // 128 or 256 rows per block

    extern __shared__ float sm[];
    float*  Ws = sm;                                        // [K][OUTD]
    float2* zs = reinterpret_cast<float2*>(sm + K * OUTD);  // [ROWS][BK+1] duplicated

    const int t = threadIdx.x;
    const int tx = t % G;
    const int ty = t / G;
    const int rowbase = blockIdx.x * ROWS;

    // stage full W once
    for (int i = t; i < K * OUTD / 4; i += 256)
        ((float4*)Ws)[i] = ((const float4*)W)[i];

    float2 acc[8][2];
#pragma unroll
    for (int i = 0; i < 8; i++) { acc[i][0] = make_float2(0.f, 0.f); acc[i][1] = make_float2(0.f, 0.f); }

    for (int kb = 0; kb < K; kb += BK) {
        __syncthreads();
        constexpr int PASSES = ROWS / 32;
#pragma unroll
        for (int ps = 0; ps < PASSES; ps++) {
            int rl = ps * 32 + t / 8;
            int f4 = t % 8;
            int r = rowbase + rl;
            float4 zv = make_float4(0.f, 0.f, 0.f, 0.f);
            if (r < nrows) zv = *(const float4*)(Z + (size_t)r * K + kb + f4 * 4);
            float2* d = zs + rl * (BK + 1) + f4 * 4;
            d[0] = make_float2(zv.x, zv.x);
            d[1] = make_float2(zv.y, zv.y);
            d[2] = make_float2(zv.z, zv.z);
            d[3] = make_float2(zv.w, zv.w);
        }
        __syncthreads();
#pragma unroll
        for (int k = 0; k < BK; k++) {
            const float* wr = Ws + (kb + k) * OUTD + tx * 4;
            float2 w0 = *(const float2*)wr;
            float2 w1 = *(const float2*)(wr + 2);
#pragma unroll
            for (int i = 0; i < 8; i++) {
                float2 zd = zs[(i * TY + ty) * (BK + 1) + k];
                acc[i][0] = ffma2(zd, w0, acc[i][0]);
                acc[i][1] = ffma2(zd, w1, acc[i][1]);
            }
        }
    }

    float4 bv = *(const float4*)(bias + tx * 4);
#pragma unroll
    for (int i = 0; i < 8; i++) {
        int r = rowbase + i * TY + ty;
        if (r < nrows) {
            float4 o = make_float4(acc[i][0].x + bv.x, acc[i][0].y + bv.y,
                                   acc[i][1].x + bv.z, acc[i][1].y + bv.w);
            if (RELU) {
                o.x = fmaxf(o.x, 0.f); o.y = fmaxf(o.y, 0.f);
                o.z = fmaxf(o.z, 0.f); o.w = fmaxf(o.w, 0.f);
            }
            *(float4*)(C + (size_t)r * OUTD + tx * 4) = o;
        }
    }
}

// ---------------- host launcher ----------------
extern "C" void kernel_launch(void* const* d_in, const int* in_sizes, int n_in,
                              void* d_out, int out_size) {
    const int*   input_nodes = (const int*)d_in[0];
    const int*   src1  = (const int*)d_in[1];
    const int*   dst1  = (const int*)d_in[2];
    const int*   etyp1 = (const int*)d_in[3];
    const float* norm1 = (const float*)d_in[4];
    const int*   src2  = (const int*)d_in[5];
    const int*   dst2  = (const int*)d_in[6];
    const int*   etyp2 = (const int*)d_in[7];
    const float* norm2 = (const float*)d_in[8];
    const float* emb   = (const float*)d_in[9];
    const float* V1    = (const float*)d_in[10];
    const float* comp1 = (const float*)d_in[11];
    const float* b1    = (const float*)d_in[12];
    const float* V2    = (const float*)d_in[13];
    const float* comp2 = (const float*)d_in[14];
    const float* b2    = (const float*)d_in[15];
    float* out = (float*)d_out;

    void *p;
    int *rowptr1, *cursor1, *perm1, *rowptr2, *cursor2, *perm2, *bs1, *bs2;
    float *z1, *h, *z2;
    cudaGetSymbolAddress(&p, g_rowptr1); rowptr1 = (int*)p;
    cudaGetSymbolAddress(&p, g_cursor1); cursor1 = (int*)p;
    cudaGetSymbolAddress(&p, g_perm1);   perm1   = (int*)p;
    cudaGetSymbolAddress(&p, g_rowptr2); rowptr2 = (int*)p;
    cudaGetSymbolAddress(&p, g_cursor2); cursor2 = (int*)p;
    cudaGetSymbolAddress(&p, g_perm2);   perm2   = (int*)p;
    cudaGetSymbolAddress(&p, g_bs1);     bs1     = (int*)p;
    cudaGetSymbolAddress(&p, g_bs2);     bs2     = (int*)p;
    cudaGetSymbolAddress(&p, g_z1);      z1      = (float*)p;
    cudaGetSymbolAddress(&p, g_h);       h       = (float*)p;
    cudaGetSymbolAddress(&p, g_z2);      z2      = (float*)p;

    const int smem1 = 256 * 64 * 4 + 128 * 33 * 8;   // 99328 B
    const int smem2 = 256 * 32 * 4 + 256 * 33 * 8;   // 100352 B
    cudaFuncSetAttribute(k_gemm<64, true>,  cudaFuncAttributeMaxDynamicSharedMemorySize, smem1);
    cudaFuncSetAttribute(k_gemm<32, false>, cudaFuncAttributeMaxDynamicSharedMemorySize, smem2);

    const int nb1 = (N1C + 2047) / 2048;   // 49
    const int nb2 = (N2C + 2047) / 2048;   // 10

    // --- counting sort by dst (both layers) ---
    k_zero<<<(N1C + 256) / 256, 256>>>(cursor1, N1C, cursor2, N2C);
    k_hist<<<(E1C + E2C + 255) / 256, 256>>>(dst1, dst2, cursor1, cursor2);
    k_scan_local<<<nb1, 256>>>(cursor1, rowptr1, bs1, N1C);
    k_scan_local<<<nb2, 256>>>(cursor2, rowptr2, bs2, N2C);
    k_scan_bsums2<<<2, 64>>>(bs1, nb1, bs2, nb2);
    k_scan_add<<<(N1C + 255) / 256, 256>>>(rowptr1, cursor1, bs1, N1C, E1C);
    k_scan_add<<<(N2C + 255) / 256, 256>>>(rowptr2, cursor2, bs2, N2C, E2C);
    k_scatter<<<(E1C + E2C + 255) / 256, 256>>>(dst1, dst2, cursor1, cursor2, perm1, perm2);

    // --- layer 1: aggregate -> project ---
    k_agg<<<(N1C * 32 + 255) / 256, 256>>>(rowptr1, perm1, src1, etyp1, norm1,
                                           input_nodes, emb, comp1, z1, N1C);
    k_gemm<64, true><<<(N1C + 127) / 128, 256, smem1>>>(z1, V1, b1, h, N1C);

    // --- layer 2: aggregate -> project ---
    k_agg<<<(N2C * 32 + 255) / 256, 256>>>(rowptr2, perm2, src2, etyp2, norm2,
                                           nullptr, h, comp2, z2, N2C);
    k_gemm<32, false><<<(N2C + 255) / 256, 256, smem2>>>(z2, V2, b2, out, N2C);
}